// round 2
// baseline (speedup 1.0000x reference)
#include <cuda_runtime.h>

#define H_IMG 512
#define W_IMG 512
#define NMAX  2048
#define TILE  16
#define TX_N  (W_IMG / TILE)   /* 32 */
#define TY_N  (H_IMG / TILE)   /* 32 */
#define NTILES (TX_N * TY_N)   /* 1024 */
#define CHUNK 256

#define TWO_PI_F        6.28318530717958647692f
#define LOG2E_F         1.44269504088896340736f
#define LOG2_ALPHA_MIN  -7.99435344f   /* log2(1/255) */
#define ALPHA_MAX_F     0.999f

// Per-gaussian precomputed parameters
__device__ float4 g_P0[NMAX];          // mx, my, A(=0.5*c0), B(=0.5*c2)
__device__ float4 g_P1[NMAX];          // C(=c1), L(=log2(op)), fr, fg
__device__ float  g_FB[NMAX];          // fb
// Per-tile gaussian lists
__device__ int    g_tile_cnt[NTILES];          // zero-init at load; render re-zeroes
__device__ int    g_tile_list[NTILES][NMAX];   // 8 MB static scratch

__global__ void prep_bin_kernel(const float* __restrict__ xyz,
                                const float* __restrict__ scaling,
                                const float* __restrict__ rot,
                                const float* __restrict__ feat,
                                const float* __restrict__ opac,
                                int N)
{
    int i = blockIdx.x * blockDim.x + threadIdx.x;
    if (i >= N) return;

    float theta = (1.0f / (1.0f + expf(-rot[i]))) * TWO_PI_F;
    float s0 = fabsf(scaling[2*i + 0]); s0 *= s0;
    float s1 = fabsf(scaling[2*i + 1]); s1 *= s1;
    float cs = cosf(theta);
    float sn = sinf(theta);

    float a = cs*cs*s0 + sn*sn*s1;
    float b = cs*sn*(s0 - s1);
    float c = sn*sn*s0 + cs*cs*s1;
    float inv_det = 1.0f / (a*c - b*b);
    float c0 =  c * inv_det;
    float c1 = -b * inv_det;
    float c2 =  a * inv_det;

    float mx = 0.5f * ((xyz[2*i + 0] + 1.0f) * (float)W_IMG - 1.0f);
    float my = 0.5f * ((xyz[2*i + 1] + 1.0f) * (float)H_IMG - 1.0f);

    float op = opac[i];
    float L  = log2f(op);                 // alpha = 2^(L - sigma*log2e)
    float lnthr = logf(op * 255.0f);      // contributes iff sigma <= lnthr
    float smax  = fmaxf(s0, s1);          // lambda_max(Sigma) upper bound
    // sigma >= 0.5*dist^2/smax  =>  contributes only if dist^2 <= 2*smax*lnthr
    float r2 = (lnthr > 0.0f) ? (2.0f * smax * lnthr) : -1.0f;

    g_P0[i] = make_float4(mx, my, 0.5f * c0, 0.5f * c2);
    g_P1[i] = make_float4(c1, L, feat[3*i + 0], feat[3*i + 1]);
    g_FB[i] = feat[3*i + 2];

    if (r2 <= 0.0f) return;
    float r = sqrtf(r2);

    int tx_lo = max(0,        (int)floorf((mx - r) * (1.0f / TILE)));
    int tx_hi = min(TX_N - 1, (int)floorf((mx + r) * (1.0f / TILE)));
    int ty_lo = max(0,        (int)floorf((my - r) * (1.0f / TILE)));
    int ty_hi = min(TY_N - 1, (int)floorf((my + r) * (1.0f / TILE)));

    for (int ty = ty_lo; ty <= ty_hi; ++ty) {
        float by0 = (float)(ty * TILE);
        float dyb = fmaxf(0.0f, fmaxf(by0 - my, my - (by0 + (TILE - 1))));
        float dyb2 = dyb * dyb;
        for (int tx = tx_lo; tx <= tx_hi; ++tx) {
            float bx0 = (float)(tx * TILE);
            float dxb = fmaxf(0.0f, fmaxf(bx0 - mx, mx - (bx0 + (TILE - 1))));
            if (fmaf(dxb, dxb, dyb2) <= r2) {
                int t = ty * TX_N + tx;
                int pos = atomicAdd(&g_tile_cnt[t], 1);
                g_tile_list[t][pos] = i;
            }
        }
    }
}

__global__ __launch_bounds__(256, 6)
void render_kernel(float* __restrict__ out)
{
    __shared__ float4 sP0[CHUNK];
    __shared__ float4 sP1[CHUNK];
    __shared__ float  sFB[CHUNK];

    const int tid = threadIdx.x;
    const int tx  = tid & (TILE - 1);
    const int ty  = tid >> 4;

    const int tile = blockIdx.y * TX_N + blockIdx.x;
    const int px = blockIdx.x * TILE + tx;
    const int py = blockIdx.y * TILE + ty;
    const float fx = (float)px;
    const float fy = (float)py;

    const int cnt = g_tile_cnt[tile];

    float accr = 0.0f, accg = 0.0f, accb = 0.0f;

    for (int base = 0; base < cnt; base += CHUNK) {
        int k = base + tid;
        if (k < cnt) {
            int g = g_tile_list[tile][k];
            sP0[tid] = g_P0[g];
            sP1[tid] = g_P1[g];
            sFB[tid] = g_FB[g];
        }
        __syncthreads();

        int m = cnt - base;
        if (m > CHUNK) m = CHUNK;

        #pragma unroll 4
        for (int j = 0; j < m; ++j) {
            float4 Q0 = sP0[j];
            float4 Q1 = sP1[j];
            float  qb = sFB[j];
            float dx = fx - Q0.x;
            float dy = fy - Q0.y;
            // sigma = A*dx^2 + B*dy^2 + C*dx*dy
            float t     = fmaf(Q1.x, dy, Q0.z * dx);   // C*dy + A*dx
            float sigma = fmaf(Q0.w * dy, dy, t * dx); // B*dy^2 + dx*(...)
            // alpha = op*exp(-sigma) = 2^(L - sigma*log2e)
            float arg = fmaf(sigma, -LOG2E_F, Q1.y);
            float alpha;
            asm("ex2.approx.ftz.f32 %0, %1;" : "=f"(alpha) : "f"(arg));
            alpha = fminf(alpha, ALPHA_MAX_F);
            if (arg >= LOG2_ALPHA_MIN) {   // alpha_raw >= 1/255
                accr = fmaf(alpha, Q1.z, accr);
                accg = fmaf(alpha, Q1.w, accg);
                accb = fmaf(alpha, qb,   accb);
            }
        }
        __syncthreads();   // safe to overwrite shared next chunk
    }

    // leave counter zeroed for the next launch (module-load init covers call 1)
    if (tid == 0) g_tile_cnt[tile] = 0;

    // out layout: [1, 3, H, W]
    out[(0 * H_IMG + py) * W_IMG + px] = fminf(fmaxf(accr, 0.0f), 1.0f);
    out[(1 * H_IMG + py) * W_IMG + px] = fminf(fmaxf(accg, 0.0f), 1.0f);
    out[(2 * H_IMG + py) * W_IMG + px] = fminf(fmaxf(accb, 0.0f), 1.0f);
}

extern "C" void kernel_launch(void* const* d_in, const int* in_sizes, int n_in,
                              void* d_out, int out_size)
{
    const float* xyz     = (const float*)d_in[0];
    const float* scaling = (const float*)d_in[1];
    const float* rot     = (const float*)d_in[2];
    const float* feat    = (const float*)d_in[3];
    const float* opac    = (const float*)d_in[4];
    float* out = (float*)d_out;

    int N = in_sizes[0] / 2;
    if (N > NMAX) N = NMAX;

    prep_bin_kernel<<<(N + 255) / 256, 256>>>(xyz, scaling, rot, feat, opac, N);

    dim3 grid(TX_N, TY_N);
    render_kernel<<<grid, 256>>>(out);
}

// round 3
// speedup vs baseline: 1.9552x; 1.9552x over previous
#include <cuda_runtime.h>

#define H_IMG 512
#define W_IMG 512
#define NMAX  2048
#define TILE  16
#define TX_N  (W_IMG / TILE)   /* 32 */
#define TY_N  (H_IMG / TILE)   /* 32 */
#define NTILES (TX_N * TY_N)   /* 1024 */
#define CHUNK 256
#define BIN_T 64               /* threads per gaussian in bin kernel */

#define TWO_PI_F        6.28318530717958647692f
#define LOG2E_F         1.44269504088896340736f
#define LOG2_ALPHA_MIN  -7.99435344f   /* log2(1/255) */
#define ALPHA_MAX_F     0.999f

// Per-gaussian precomputed parameters
__device__ float4 g_P0[NMAX];          // mx, my, A(=0.5*c0), B(=0.5*c2)
__device__ float4 g_P1[NMAX];          // C(=c1), L(=log2(op)), fr, fg
__device__ float  g_FB[NMAX];          // fb
__device__ float4 g_BB[NMAX];          // mx, my, r2, r
// Per-tile gaussian lists
__device__ int    g_tile_cnt[NTILES];          // zero at load; render re-zeroes
__device__ int    g_tile_list[NTILES][NMAX];   // 8 MB static scratch

__global__ void prep_kernel(const float* __restrict__ xyz,
                            const float* __restrict__ scaling,
                            const float* __restrict__ rot,
                            const float* __restrict__ feat,
                            const float* __restrict__ opac,
                            int N)
{
    int i = blockIdx.x * blockDim.x + threadIdx.x;
    if (i >= N) return;

    float theta = (1.0f / (1.0f + expf(-rot[i]))) * TWO_PI_F;
    float s0 = fabsf(scaling[2*i + 0]); s0 *= s0;
    float s1 = fabsf(scaling[2*i + 1]); s1 *= s1;
    float cs = cosf(theta);
    float sn = sinf(theta);

    float a = cs*cs*s0 + sn*sn*s1;
    float b = cs*sn*(s0 - s1);
    float c = sn*sn*s0 + cs*cs*s1;
    float inv_det = 1.0f / (a*c - b*b);
    float c0 =  c * inv_det;
    float c1 = -b * inv_det;
    float c2 =  a * inv_det;

    float mx = 0.5f * ((xyz[2*i + 0] + 1.0f) * (float)W_IMG - 1.0f);
    float my = 0.5f * ((xyz[2*i + 1] + 1.0f) * (float)H_IMG - 1.0f);

    float op = opac[i];
    float L  = log2f(op);                 // alpha = 2^(L - sigma*log2e)
    float lnthr = logf(op * 255.0f);      // contributes iff sigma <= lnthr
    float smax  = fmaxf(s0, s1);          // lambda_max(Sigma) upper bound
    // sigma >= 0.5*dist^2/smax  =>  contributes only if dist^2 <= 2*smax*lnthr
    float r2 = (lnthr > 0.0f) ? (2.0f * smax * lnthr) : -1.0f;
    float r  = (r2 > 0.0f) ? sqrtf(r2) : 0.0f;

    g_P0[i] = make_float4(mx, my, 0.5f * c0, 0.5f * c2);
    g_P1[i] = make_float4(c1, L, feat[3*i + 0], feat[3*i + 1]);
    g_FB[i] = feat[3*i + 2];
    g_BB[i] = make_float4(mx, my, r2, r);
}

__global__ void bin_kernel(int N)
{
    int gt = blockIdx.x * blockDim.x + threadIdx.x;
    int g  = gt / BIN_T;
    int s  = gt & (BIN_T - 1);
    if (g >= N) return;

    float4 bb = g_BB[g];
    float r2 = bb.z;
    if (r2 <= 0.0f) return;
    float mx = bb.x, my = bb.y, r = bb.w;

    int tx_lo = max(0,        (int)floorf((mx - r) * (1.0f / TILE)));
    int tx_hi = min(TX_N - 1, (int)floorf((mx + r) * (1.0f / TILE)));
    int ty_lo = max(0,        (int)floorf((my - r) * (1.0f / TILE)));
    int ty_hi = min(TY_N - 1, (int)floorf((my + r) * (1.0f / TILE)));
    if (tx_hi < tx_lo || ty_hi < ty_lo) return;

    int w = tx_hi - tx_lo + 1;
    int h = ty_hi - ty_lo + 1;
    int cand = w * h;

    for (int sidx = s; sidx < cand; sidx += BIN_T) {
        int tx = tx_lo + (sidx % w);
        int ty = ty_lo + (sidx / w);
        float bx0 = (float)(tx * TILE);
        float by0 = (float)(ty * TILE);
        float dxb = fmaxf(0.0f, fmaxf(bx0 - mx, mx - (bx0 + (TILE - 1))));
        float dyb = fmaxf(0.0f, fmaxf(by0 - my, my - (by0 + (TILE - 1))));
        if (fmaf(dxb, dxb, dyb * dyb) <= r2) {
            int t = ty * TX_N + tx;
            int pos = atomicAdd(&g_tile_cnt[t], 1);
            g_tile_list[t][pos] = g;
        }
    }
}

// 128 threads/CTA, each thread renders 2 pixels: (px, py) and (px, py+8)
__global__ __launch_bounds__(128, 8)
void render_kernel(float* __restrict__ out)
{
    __shared__ float4 sP0[CHUNK];
    __shared__ float4 sP1[CHUNK];
    __shared__ float  sFB[CHUNK];

    const int tid = threadIdx.x;
    const int tx  = tid & (TILE - 1);
    const int ty  = tid >> 4;            // 0..7

    const int tile = blockIdx.y * TX_N + blockIdx.x;
    const int px  = blockIdx.x * TILE + tx;
    const int py0 = blockIdx.y * TILE + ty;
    const int py1 = py0 + 8;
    const float fx  = (float)px;
    const float fy0 = (float)py0;

    const int cnt = g_tile_cnt[tile];

    float ar0 = 0.0f, ag0 = 0.0f, ab0 = 0.0f;
    float ar1 = 0.0f, ag1 = 0.0f, ab1 = 0.0f;

    for (int base = 0; base < cnt; base += CHUNK) {
        int m = cnt - base;
        if (m > CHUNK) m = CHUNK;

        for (int k2 = tid; k2 < m; k2 += 128) {
            int g = g_tile_list[tile][base + k2];
            sP0[k2] = g_P0[g];
            sP1[k2] = g_P1[g];
            sFB[k2] = g_FB[g];
        }
        __syncthreads();

        #pragma unroll 4
        for (int j = 0; j < m; ++j) {
            float4 Q0 = sP0[j];
            float4 Q1 = sP1[j];
            float  qb = sFB[j];
            float dx  = fx - Q0.x;
            float dy0 = fy0 - Q0.y;
            float dy1 = dy0 + 8.0f;
            float adx = Q0.z * dx;          // A*dx (shared across both pixels)

            // pixel 0
            float t0   = fmaf(Q1.x, dy0, adx);           // C*dy0 + A*dx
            float sg0  = fmaf(Q0.w * dy0, dy0, t0 * dx); // B*dy0^2 + dx*(...)
            float arg0 = fmaf(sg0, -LOG2E_F, Q1.y);
            float al0;
            asm("ex2.approx.ftz.f32 %0, %1;" : "=f"(al0) : "f"(arg0));
            al0 = fminf(al0, ALPHA_MAX_F);
            if (arg0 >= LOG2_ALPHA_MIN) {
                ar0 = fmaf(al0, Q1.z, ar0);
                ag0 = fmaf(al0, Q1.w, ag0);
                ab0 = fmaf(al0, qb,   ab0);
            }
            // pixel 1
            float t1   = fmaf(Q1.x, dy1, adx);
            float sg1  = fmaf(Q0.w * dy1, dy1, t1 * dx);
            float arg1 = fmaf(sg1, -LOG2E_F, Q1.y);
            float al1;
            asm("ex2.approx.ftz.f32 %0, %1;" : "=f"(al1) : "f"(arg1));
            al1 = fminf(al1, ALPHA_MAX_F);
            if (arg1 >= LOG2_ALPHA_MIN) {
                ar1 = fmaf(al1, Q1.z, ar1);
                ag1 = fmaf(al1, Q1.w, ag1);
                ab1 = fmaf(al1, qb,   ab1);
            }
        }
        __syncthreads();
    }

    // leave counter zeroed for the next launch
    if (tid == 0) g_tile_cnt[tile] = 0;

    // out layout: [1, 3, H, W]
    out[(0 * H_IMG + py0) * W_IMG + px] = fminf(fmaxf(ar0, 0.0f), 1.0f);
    out[(1 * H_IMG + py0) * W_IMG + px] = fminf(fmaxf(ag0, 0.0f), 1.0f);
    out[(2 * H_IMG + py0) * W_IMG + px] = fminf(fmaxf(ab0, 0.0f), 1.0f);
    out[(0 * H_IMG + py1) * W_IMG + px] = fminf(fmaxf(ar1, 0.0f), 1.0f);
    out[(1 * H_IMG + py1) * W_IMG + px] = fminf(fmaxf(ag1, 0.0f), 1.0f);
    out[(2 * H_IMG + py1) * W_IMG + px] = fminf(fmaxf(ab1, 0.0f), 1.0f);
}

extern "C" void kernel_launch(void* const* d_in, const int* in_sizes, int n_in,
                              void* d_out, int out_size)
{
    const float* xyz     = (const float*)d_in[0];
    const float* scaling = (const float*)d_in[1];
    const float* rot     = (const float*)d_in[2];
    const float* feat    = (const float*)d_in[3];
    const float* opac    = (const float*)d_in[4];
    float* out = (float*)d_out;

    int N = in_sizes[0] / 2;
    if (N > NMAX) N = NMAX;

    prep_kernel<<<(N + 255) / 256, 256>>>(xyz, scaling, rot, feat, opac, N);
    bin_kernel<<<(N * BIN_T + 255) / 256, 256>>>(N);

    dim3 grid(TX_N, TY_N);
    render_kernel<<<grid, 128>>>(out);
}

// round 4
// speedup vs baseline: 2.2586x; 1.1552x over previous
#include <cuda_runtime.h>

#define H_IMG 512
#define W_IMG 512
#define NMAX  2048
#define TILE  16
#define TX_N  (W_IMG / TILE)   /* 32 */
#define TY_N  (H_IMG / TILE)   /* 32 */
#define NTILES (TX_N * TY_N)   /* 1024 */
#define CHUNK 256

#define TWO_PI_F        6.28318530717958647692f
#define LOG2E_F         1.44269504088896340736f
#define LOG2_ALPHA_MIN  -7.99435344f   /* log2(1/255) */
#define ALPHA_MAX_F     0.999f

// Per-gaussian precomputed parameters
__device__ float4 g_P0[NMAX];          // mx, my, A(=0.5*c0), B(=0.5*c2)
__device__ float4 g_P1[NMAX];          // C(=c1), L(=log2(op)), fr, fg
__device__ float  g_FB[NMAX];          // fb
// Per-tile gaussian lists
__device__ int    g_tile_cnt[NTILES];          // zero at load; render re-zeroes
__device__ int    g_tile_list[NTILES][NMAX];   // 8 MB static scratch

// One WARP per gaussian: all lanes redundantly compute params (broadcast loads,
// latency-bound regime), lane 0 writes them, then all 32 lanes cooperatively
// test candidate tiles and push to per-tile lists.
__global__ __launch_bounds__(256)
void prep_bin_kernel(const float* __restrict__ xyz,
                     const float* __restrict__ scaling,
                     const float* __restrict__ rot,
                     const float* __restrict__ feat,
                     const float* __restrict__ opac,
                     int N)
{
    int warp = (blockIdx.x * blockDim.x + threadIdx.x) >> 5;
    int lane = threadIdx.x & 31;
    int i = warp;
    if (i >= N) return;

    float theta = (1.0f / (1.0f + expf(-rot[i]))) * TWO_PI_F;
    float s0 = fabsf(scaling[2*i + 0]); s0 *= s0;
    float s1 = fabsf(scaling[2*i + 1]); s1 *= s1;
    float cs = cosf(theta);
    float sn = sinf(theta);

    float a = cs*cs*s0 + sn*sn*s1;
    float b = cs*sn*(s0 - s1);
    float c = sn*sn*s0 + cs*cs*s1;
    float inv_det = 1.0f / (a*c - b*b);
    float c0 =  c * inv_det;
    float c1 = -b * inv_det;
    float c2 =  a * inv_det;

    float mx = 0.5f * ((xyz[2*i + 0] + 1.0f) * (float)W_IMG - 1.0f);
    float my = 0.5f * ((xyz[2*i + 1] + 1.0f) * (float)H_IMG - 1.0f);

    float op = opac[i];
    float L  = log2f(op);                 // alpha = 2^(L - sigma*log2e)
    float lnthr = logf(op * 255.0f);      // contributes iff sigma <= lnthr
    float smax  = fmaxf(s0, s1);          // lambda_max(Sigma) upper bound
    // sigma >= 0.5*dist^2/smax  =>  contributes only if dist^2 <= 2*smax*lnthr
    float r2 = (lnthr > 0.0f) ? (2.0f * smax * lnthr) : -1.0f;

    if (lane == 0) {
        g_P0[i] = make_float4(mx, my, 0.5f * c0, 0.5f * c2);
        g_P1[i] = make_float4(c1, L, feat[3*i + 0], feat[3*i + 1]);
        g_FB[i] = feat[3*i + 2];
    }

    if (r2 <= 0.0f) return;
    float r = sqrtf(r2);

    int tx_lo = max(0,        (int)floorf((mx - r) * (1.0f / TILE)));
    int tx_hi = min(TX_N - 1, (int)floorf((mx + r) * (1.0f / TILE)));
    int ty_lo = max(0,        (int)floorf((my - r) * (1.0f / TILE)));
    int ty_hi = min(TY_N - 1, (int)floorf((my + r) * (1.0f / TILE)));
    if (tx_hi < tx_lo || ty_hi < ty_lo) return;

    int w = tx_hi - tx_lo + 1;
    int cand = w * (ty_hi - ty_lo + 1);

    for (int sidx = lane; sidx < cand; sidx += 32) {
        int tx = tx_lo + (sidx % w);
        int ty = ty_lo + (sidx / w);
        float bx0 = (float)(tx * TILE);
        float by0 = (float)(ty * TILE);
        float dxb = fmaxf(0.0f, fmaxf(bx0 - mx, mx - (bx0 + (TILE - 1))));
        float dyb = fmaxf(0.0f, fmaxf(by0 - my, my - (by0 + (TILE - 1))));
        if (fmaf(dxb, dxb, dyb * dyb) <= r2) {
            int t = ty * TX_N + tx;
            int pos = atomicAdd(&g_tile_cnt[t], 1);
            g_tile_list[t][pos] = i;
        }
    }
}

// 64 threads/CTA, each thread renders a 2x2 quad at stride 8:
// (px, py), (px+8, py), (px, py+8), (px+8, py+8)
__global__ __launch_bounds__(64, 16)
void render_kernel(float* __restrict__ out)
{
    __shared__ float4 sP0[CHUNK];
    __shared__ float4 sP1[CHUNK];
    __shared__ float  sFB[CHUNK];

    const int tid = threadIdx.x;
    const int tx  = tid & 7;             // 0..7
    const int ty  = tid >> 3;            // 0..7

    const int tile = blockIdx.y * TX_N + blockIdx.x;
    const int px0 = blockIdx.x * TILE + tx;
    const int py0 = blockIdx.y * TILE + ty;
    const float fx0 = (float)px0;
    const float fy0 = (float)py0;

    const int cnt = g_tile_cnt[tile];

    float a00r = 0.0f, a00g = 0.0f, a00b = 0.0f;   // (x, y)
    float a10r = 0.0f, a10g = 0.0f, a10b = 0.0f;   // (x+8, y)
    float a01r = 0.0f, a01g = 0.0f, a01b = 0.0f;   // (x, y+8)
    float a11r = 0.0f, a11g = 0.0f, a11b = 0.0f;   // (x+8, y+8)

    for (int base = 0; base < cnt; base += CHUNK) {
        int m = cnt - base;
        if (m > CHUNK) m = CHUNK;

        for (int k2 = tid; k2 < m; k2 += 64) {
            int g = g_tile_list[tile][base + k2];
            sP0[k2] = g_P0[g];
            sP1[k2] = g_P1[g];
            sFB[k2] = g_FB[g];
        }
        __syncthreads();

        #pragma unroll 2
        for (int j = 0; j < m; ++j) {
            float4 Q0 = sP0[j];
            float4 Q1 = sP1[j];
            float  qb = sFB[j];
            float dx0 = fx0 - Q0.x;
            float dx1 = dx0 + 8.0f;
            float dy0 = fy0 - Q0.y;
            float dy1 = dy0 + 8.0f;

            float adx0 = Q0.z * dx0;            // A*dx (shared per column)
            float adx1 = Q0.z * dx1;
            float bdy0 = (Q0.w * dy0) * dy0;    // B*dy^2 (shared per row)
            float bdy1 = (Q0.w * dy1) * dy1;

            // sigma = (C*dy + A*dx)*dx + B*dy^2 ; arg = L - sigma*log2e
            float t00 = fmaf(Q1.x, dy0, adx0);
            float t10 = fmaf(Q1.x, dy0, adx1);
            float t01 = fmaf(Q1.x, dy1, adx0);
            float t11 = fmaf(Q1.x, dy1, adx1);
            float s00 = fmaf(t00, dx0, bdy0);
            float s10 = fmaf(t10, dx1, bdy0);
            float s01 = fmaf(t01, dx0, bdy1);
            float s11 = fmaf(t11, dx1, bdy1);
            float g00 = fmaf(s00, -LOG2E_F, Q1.y);
            float g10 = fmaf(s10, -LOG2E_F, Q1.y);
            float g01 = fmaf(s01, -LOG2E_F, Q1.y);
            float g11 = fmaf(s11, -LOG2E_F, Q1.y);

            float e00, e10, e01, e11;
            asm("ex2.approx.ftz.f32 %0, %1;" : "=f"(e00) : "f"(g00));
            asm("ex2.approx.ftz.f32 %0, %1;" : "=f"(e10) : "f"(g10));
            asm("ex2.approx.ftz.f32 %0, %1;" : "=f"(e01) : "f"(g01));
            asm("ex2.approx.ftz.f32 %0, %1;" : "=f"(e11) : "f"(g11));
            e00 = fminf(e00, ALPHA_MAX_F);
            e10 = fminf(e10, ALPHA_MAX_F);
            e01 = fminf(e01, ALPHA_MAX_F);
            e11 = fminf(e11, ALPHA_MAX_F);

            if (g00 >= LOG2_ALPHA_MIN) {
                a00r = fmaf(e00, Q1.z, a00r);
                a00g = fmaf(e00, Q1.w, a00g);
                a00b = fmaf(e00, qb,   a00b);
            }
            if (g10 >= LOG2_ALPHA_MIN) {
                a10r = fmaf(e10, Q1.z, a10r);
                a10g = fmaf(e10, Q1.w, a10g);
                a10b = fmaf(e10, qb,   a10b);
            }
            if (g01 >= LOG2_ALPHA_MIN) {
                a01r = fmaf(e01, Q1.z, a01r);
                a01g = fmaf(e01, Q1.w, a01g);
                a01b = fmaf(e01, qb,   a01b);
            }
            if (g11 >= LOG2_ALPHA_MIN) {
                a11r = fmaf(e11, Q1.z, a11r);
                a11g = fmaf(e11, Q1.w, a11g);
                a11b = fmaf(e11, qb,   a11b);
            }
        }
        __syncthreads();
    }

    // leave counter zeroed for the next launch
    if (tid == 0) g_tile_cnt[tile] = 0;

    const int px1 = px0 + 8;
    const int py1 = py0 + 8;
    // out layout: [1, 3, H, W]
    out[(0 * H_IMG + py0) * W_IMG + px0] = fminf(fmaxf(a00r, 0.0f), 1.0f);
    out[(0 * H_IMG + py0) * W_IMG + px1] = fminf(fmaxf(a10r, 0.0f), 1.0f);
    out[(0 * H_IMG + py1) * W_IMG + px0] = fminf(fmaxf(a01r, 0.0f), 1.0f);
    out[(0 * H_IMG + py1) * W_IMG + px1] = fminf(fmaxf(a11r, 0.0f), 1.0f);
    out[(1 * H_IMG + py0) * W_IMG + px0] = fminf(fmaxf(a00g, 0.0f), 1.0f);
    out[(1 * H_IMG + py0) * W_IMG + px1] = fminf(fmaxf(a10g, 0.0f), 1.0f);
    out[(1 * H_IMG + py1) * W_IMG + px0] = fminf(fmaxf(a01g, 0.0f), 1.0f);
    out[(1 * H_IMG + py1) * W_IMG + px1] = fminf(fmaxf(a11g, 0.0f), 1.0f);
    out[(2 * H_IMG + py0) * W_IMG + px0] = fminf(fmaxf(a00b, 0.0f), 1.0f);
    out[(2 * H_IMG + py0) * W_IMG + px1] = fminf(fmaxf(a10b, 0.0f), 1.0f);
    out[(2 * H_IMG + py1) * W_IMG + px0] = fminf(fmaxf(a01b, 0.0f), 1.0f);
    out[(2 * H_IMG + py1) * W_IMG + px1] = fminf(fmaxf(a11b, 0.0f), 1.0f);
}

extern "C" void kernel_launch(void* const* d_in, const int* in_sizes, int n_in,
                              void* d_out, int out_size)
{
    const float* xyz     = (const float*)d_in[0];
    const float* scaling = (const float*)d_in[1];
    const float* rot     = (const float*)d_in[2];
    const float* feat    = (const float*)d_in[3];
    const float* opac    = (const float*)d_in[4];
    float* out = (float*)d_out;

    int N = in_sizes[0] / 2;
    if (N > NMAX) N = NMAX;

    // one warp per gaussian
    prep_bin_kernel<<<(N * 32 + 255) / 256, 256>>>(xyz, scaling, rot, feat, opac, N);

    dim3 grid(TX_N, TY_N);
    render_kernel<<<grid, 64>>>(out);
}